// round 4
// baseline (speedup 1.0000x reference)
#include <cuda_runtime.h>
#include <math.h>

// CNF_9663676416569: vector field + exact divergence via weight-precomputed E.
//
// dx  = tanh(tanh([t,x] @ W1 + b1) @ W2 + b2) @ W3 + b3
// div = sum_j (1-h2_j^2) * sum_m (1-h1_m^2) * E[m,j]
//   where E[m,j] = W2[m,j] * sum_k W1[1+k, m] * W3[j, k]   (weights only)

#define Hm 512
#define Dm 64
#define MT 64           // batch rows per CTA

// scratch for E (device global: no allocations allowed)
__device__ float g_E[Hm * Hm];

// ---------------------------------------------------------------------------
// E precompute: C = W1[1:,:]^T @ W3^T  (512x512, K=64), E = W2 .* C
// ---------------------------------------------------------------------------
__global__ __launch_bounds__(256)
void compute_E_kernel(const float* __restrict__ W1,
                      const float* __restrict__ W2,
                      const float* __restrict__ W3) {
    __shared__ float As[64][33];   // As[i][ml] = W1[(1+i)*512 + m0+ml]
    __shared__ float Bs[32][65];   // Bs[jl][i] = W3[(j0+jl)*64 + i]
    const int m0 = blockIdx.x * 32;
    const int j0 = blockIdx.y * 32;
    const int tid = threadIdx.x;

    for (int p = tid; p < 64 * 32; p += 256) {
        int i = p >> 5, ml = p & 31;
        As[i][ml] = W1[(1 + i) * Hm + m0 + ml];
    }
    for (int p = tid; p < 32 * 64; p += 256) {
        int i = p & 63, jl = p >> 6;
        Bs[jl][i] = W3[(j0 + jl) * 64 + i];
    }
    __syncthreads();

    const int jl = tid & 31;       // j fast -> coalesced E writes
    const int mg = tid >> 5;       // 0..7, 4 m-rows each
    float acc[4] = {0.f, 0.f, 0.f, 0.f};
    #pragma unroll
    for (int i = 0; i < 64; i++) {
        float b = Bs[jl][i];
        #pragma unroll
        for (int q = 0; q < 4; q++)
            acc[q] = fmaf(As[i][mg * 4 + q], b, acc[q]);
    }
    #pragma unroll
    for (int q = 0; q < 4; q++) {
        int m = m0 + mg * 4 + q;
        int j = j0 + jl;
        g_E[m * Hm + j] = W2[m * Hm + j] * acc[q];
    }
}

// ---------------------------------------------------------------------------
// Main kernel: one CTA = 64 batch rows, 256 threads.
// SMEM: s_xa[64][66], s_h1t[512][66] (k-major), s_stage[64][65], s_div[64]
// ---------------------------------------------------------------------------
__global__ __launch_bounds__(256, 1)
void cnf_main_kernel(const float* __restrict__ t,
                     const float* __restrict__ x,
                     const float* __restrict__ W1,
                     const float* __restrict__ b1,
                     const float* __restrict__ W2,
                     const float* __restrict__ b2,
                     const float* __restrict__ W3,
                     const float* __restrict__ b3,
                     float* __restrict__ out) {
    extern __shared__ float sm[];
    float* s_xa    = sm;                      // 64*66  = 4224 floats
    float* s_h1t   = sm + 64 * 66;            // 512*66 = 33792 floats
    float* s_stage = s_h1t + 512 * 66;        // 64*65  = 4160 floats
    float* s_div   = s_stage + 64 * 65;       // 64 floats

    const int tid  = threadIdx.x;
    const int row0 = blockIdx.x * MT;

    if (tid < 64) s_div[tid] = 0.f;

    // ---- load [t, x] tile ----
    const float tval = t[0];
    for (int p = tid; p < 64 * 65; p += 256) {
        int r = p / 65, c = p % 65;
        s_xa[r * 66 + c] = (c == 0) ? tval : x[(size_t)(row0 + r) * 65 + (c - 1)];
    }
    __syncthreads();

    // ---- Phase A: H1 = tanh(Xa @ W1 + b1), stored transposed s_h1t[n][r] ----
    #pragma unroll
    for (int nsel = 0; nsel < 2; nsel++) {
        const int n = tid + nsel * 256;
        #pragma unroll
        for (int half = 0; half < 2; half++) {
            const int rb = half * 32;
            float acc[32];
            const float bb = b1[n];
            #pragma unroll
            for (int r = 0; r < 32; r++) acc[r] = bb;
            for (int i = 0; i < 65; i++) {
                const float w = W1[i * Hm + n];
                const float* xa = s_xa + rb * 66 + i;
                #pragma unroll
                for (int r = 0; r < 32; r++)
                    acc[r] = fmaf(xa[r * 66], w, acc[r]);
            }
            #pragma unroll
            for (int r = 0; r < 32; r++)
                s_h1t[n * 66 + rb + r] = tanhf(acc[r]);
        }
    }
    __syncthreads();

    // ---- Phase B: fused Z2 = H1@W2 + b2 and U = (1-H1^2)@E, chunked over N ----
    const int tx = tid & 15;
    const int ty = tid >> 4;
    const int r0 = ty * 4;        // 4 rows
    const int d0 = tx * 4;        // 4 cols (chunk-local / dx cols)

    float accDX[4][4];
    #pragma unroll
    for (int i = 0; i < 4; i++)
        #pragma unroll
        for (int j = 0; j < 4; j++) accDX[i][j] = 0.f;
    float divacc[4] = {0.f, 0.f, 0.f, 0.f};

    for (int ch = 0; ch < 8; ch++) {
        const int n0 = ch * 64;
        float accZ[4][4], accU[4][4];
        #pragma unroll
        for (int j = 0; j < 4; j++) {
            const float bz = b2[n0 + d0 + j];
            #pragma unroll
            for (int i = 0; i < 4; i++) { accZ[i][j] = bz; accU[i][j] = 0.f; }
        }

        const float4* __restrict__ pW2 = (const float4*)(W2  + n0 + d0);
        const float4* __restrict__ pE  = (const float4*)(g_E + n0 + d0);
        const float*  __restrict__ ph  = s_h1t + r0;

        #pragma unroll 4
        for (int k = 0; k < Hm; k++) {
            float a[4], g[4];
            #pragma unroll
            for (int i = 0; i < 4; i++) {
                a[i] = ph[k * 66 + i];
                g[i] = fmaf(-a[i], a[i], 1.f);
            }
            const float4 bz4 = pW2[(size_t)k * (Hm / 4)];
            const float4 be4 = pE [(size_t)k * (Hm / 4)];
            const float bzv[4] = {bz4.x, bz4.y, bz4.z, bz4.w};
            const float bev[4] = {be4.x, be4.y, be4.z, be4.w};
            #pragma unroll
            for (int i = 0; i < 4; i++)
                #pragma unroll
                for (int j = 0; j < 4; j++) {
                    accZ[i][j] = fmaf(a[i], bzv[j], accZ[i][j]);
                    accU[i][j] = fmaf(g[i], bev[j], accU[i][j]);
                }
        }

        // h2 / g2, div partials (registers), stage h2 for DX gemm
        #pragma unroll
        for (int i = 0; i < 4; i++) {
            #pragma unroll
            for (int j = 0; j < 4; j++) {
                const float h2 = tanhf(accZ[i][j]);
                const float g2 = fmaf(-h2, h2, 1.f);
                divacc[i] = fmaf(g2, accU[i][j], divacc[i]);
                s_stage[(r0 + i) * 65 + d0 + j] = h2;
            }
        }
        __syncthreads();

        // accDX += h2_chunk @ W3[n0:n0+64, :]
        for (int kk = 0; kk < 64; kk++) {
            const float4 w3 = *(const float4*)(W3 + (size_t)(n0 + kk) * Dm + d0);
            const float wv[4] = {w3.x, w3.y, w3.z, w3.w};
            float a[4];
            #pragma unroll
            for (int i = 0; i < 4; i++) a[i] = s_stage[(r0 + i) * 65 + kk];
            #pragma unroll
            for (int i = 0; i < 4; i++)
                #pragma unroll
                for (int j = 0; j < 4; j++)
                    accDX[i][j] = fmaf(a[i], wv[j], accDX[i][j]);
        }
        __syncthreads();
    }

    // ---- epilogue ----
    #pragma unroll
    for (int i = 0; i < 4; i++) atomicAdd(&s_div[r0 + i], divacc[i]);

    #pragma unroll
    for (int i = 0; i < 4; i++) {
        const size_t ro = (size_t)(row0 + r0 + i) * 65;
        #pragma unroll
        for (int j = 0; j < 4; j++)
            out[ro + d0 + j] = accDX[i][j] + b3[d0 + j];
    }
    __syncthreads();
    if (tid < 64)
        out[(size_t)(row0 + tid) * 65 + 64] = s_div[tid];
}

// ---------------------------------------------------------------------------
extern "C" void kernel_launch(void* const* d_in, const int* in_sizes, int n_in,
                              void* d_out, int out_size) {
    const float* t  = (const float*)d_in[0];
    const float* x  = (const float*)d_in[1];
    const float* W1 = (const float*)d_in[2];
    const float* b1 = (const float*)d_in[3];
    const float* W2 = (const float*)d_in[4];
    const float* b2 = (const float*)d_in[5];
    const float* W3 = (const float*)d_in[6];
    const float* b3 = (const float*)d_in[7];
    float* out = (float*)d_out;

    compute_E_kernel<<<dim3(16, 16), 256>>>(W1, W2, W3);

    const int smem_bytes = (64 * 66 + 512 * 66 + 64 * 65 + 64) * (int)sizeof(float);
    cudaFuncSetAttribute(cnf_main_kernel,
                         cudaFuncAttributeMaxDynamicSharedMemorySize, smem_bytes);
    cnf_main_kernel<<<8192 / MT, 256, smem_bytes>>>(t, x, W1, b1, W2, b2, W3, b3, out);
}

// round 6
// speedup vs baseline: 1.3259x; 1.3259x over previous
#include <cuda_runtime.h>
#include <math.h>

// CNF_9663676416569: vector field + exact divergence via weight-precomputed E.
//
// dx  = tanh(tanh([t,x] @ W1 + b1) @ W2 + b2) @ W3 + b3
// div = sum_j (1-h2_j^2) * sum_m (1-h1_m^2) * E[m,j]
//   where E[m,j] = W2[m,j] * sum_k W1[1+k, m] * W3[j, k]   (weights only)
//
// R5: packed fp32 (fma.rn.f32x2 / FFMA2), MT=32 + 2 CTAs/SM (grid 256),
//     LDS.64 A-operands, j-packed accumulators so B-operands need no packing.

#define Hm 512
#define Dm 64
#define MT 32
#define H1P 34          // s_h1t pitch (rows 32 + pad), even -> LDS.64 aligned
#define STP 34          // s_st pitch

typedef unsigned long long ull;

__device__ float g_E[Hm * Hm];

__device__ __forceinline__ ull pack2(float lo, float hi) {
    ull d; asm("mov.b64 %0, {%1, %2};" : "=l"(d) : "f"(lo), "f"(hi)); return d;
}
__device__ __forceinline__ void unpack2(ull v, float& lo, float& hi) {
    asm("mov.b64 {%0, %1}, %2;" : "=f"(lo), "=f"(hi) : "l"(v));
}
__device__ __forceinline__ void ffma2(ull& d, ull a, ull b) {
    asm("fma.rn.f32x2 %0, %1, %2, %0;" : "+l"(d) : "l"(a), "l"(b));
}

// ---------------------------------------------------------------------------
// E precompute: C = W1[1:,:]^T @ W3^T  (512x512, K=64), E = W2 .* C
// ---------------------------------------------------------------------------
__global__ __launch_bounds__(256)
void compute_E_kernel(const float* __restrict__ W1,
                      const float* __restrict__ W2,
                      const float* __restrict__ W3) {
    __shared__ float As[64][33];
    __shared__ float Bs[32][65];
    const int m0 = blockIdx.x * 32;
    const int j0 = blockIdx.y * 32;
    const int tid = threadIdx.x;

    for (int p = tid; p < 64 * 32; p += 256) {
        int i = p >> 5, ml = p & 31;
        As[i][ml] = W1[(1 + i) * Hm + m0 + ml];
    }
    for (int p = tid; p < 32 * 64; p += 256) {
        int i = p & 63, jl = p >> 6;
        Bs[jl][i] = W3[(j0 + jl) * 64 + i];
    }
    __syncthreads();

    const int jl = tid & 31;
    const int mg = tid >> 5;
    float acc[4] = {0.f, 0.f, 0.f, 0.f};
    #pragma unroll
    for (int i = 0; i < 64; i++) {
        float b = Bs[jl][i];
        #pragma unroll
        for (int q = 0; q < 4; q++)
            acc[q] = fmaf(As[i][mg * 4 + q], b, acc[q]);
    }
    #pragma unroll
    for (int q = 0; q < 4; q++) {
        int m = m0 + mg * 4 + q;
        int j = j0 + jl;
        g_E[m * Hm + j] = W2[m * Hm + j] * acc[q];
    }
}

// ---------------------------------------------------------------------------
// Main kernel: one CTA = 32 batch rows, 256 threads, 2 CTAs/SM.
// SMEM: s_xaT[65][32] (transposed), s_h1t[512][34] (k-major),
//       s_st[64][34] (h2 transposed [j][r]), s_div[32]
// ---------------------------------------------------------------------------
__global__ __launch_bounds__(256, 2)
void cnf_main_kernel(const float* __restrict__ t,
                     const float* __restrict__ x,
                     const float* __restrict__ W1,
                     const float* __restrict__ b1,
                     const float* __restrict__ W2,
                     const float* __restrict__ b2,
                     const float* __restrict__ W3,
                     const float* __restrict__ b3,
                     float* __restrict__ out) {
    extern __shared__ float sm[];
    float* s_xaT = sm;                        // 65*32  = 2080
    float* s_h1t = sm + 65 * 32;              // 512*34 = 17408
    float* s_st  = s_h1t + 512 * H1P;         // 64*34  = 2176
    float* s_div = s_st + 64 * STP;           // 32

    const int tid  = threadIdx.x;
    const int row0 = blockIdx.x * MT;

    if (tid < MT) s_div[tid] = 0.f;

    // ---- load [t, x] tile, transposed: s_xaT[c][r] ----
    const float tval = t[0];
    for (int p = tid; p < 65 * 32; p += 256) {
        int c = p >> 5, r = p & 31;
        s_xaT[c * 32 + r] = (c == 0) ? tval
                                     : x[(size_t)(row0 + r) * 65 + (c - 1)];
    }
    __syncthreads();

    // ---- Phase A: H1 = tanh(Xa @ W1 + b1), packed over row-pairs ----
    #pragma unroll
    for (int nsel = 0; nsel < 2; nsel++) {
        const int n = tid + nsel * 256;
        const float bb = b1[n];
        const ull pb = pack2(bb, bb);
        ull acc2[16];
        #pragma unroll
        for (int p = 0; p < 16; p++) acc2[p] = pb;
        for (int c = 0; c < 65; c++) {
            const float w = W1[c * Hm + n];
            const ull pw = pack2(w, w);
            const ull* xa = (const ull*)(s_xaT + c * 32);
            #pragma unroll
            for (int p = 0; p < 16; p++) ffma2(acc2[p], xa[p], pw);
        }
        float* dst = s_h1t + n * H1P;
        #pragma unroll
        for (int p = 0; p < 16; p++) {
            float lo, hi; unpack2(acc2[p], lo, hi);
            *(float2*)(dst + 2 * p) = make_float2(tanhf(lo), tanhf(hi));
        }
    }
    __syncthreads();

    // ---- Phase B: fused Z2 = H1@W2 + b2 and U = (1-H1^2)@E ----
    const int tx = tid & 15;
    const int ty = tid >> 4;
    const int r0 = ty * 2;        // 2 rows per thread (even -> LDS.64 ok)
    const int d0 = tx * 4;        // 4 cols per thread (j-packed in pairs)

    ull accDX[2][2];
    accDX[0][0] = accDX[0][1] = accDX[1][0] = accDX[1][1] = 0ull;
    float dv0 = 0.f, dv1 = 0.f;

    for (int ch = 0; ch < 8; ch++) {
        const int n0 = ch * 64;

        const ulonglong2 pb2v = *(const ulonglong2*)(b2 + n0 + d0);
        ull accZ[2][2], accU[2][2];
        accZ[0][0] = pb2v.x; accZ[0][1] = pb2v.y;
        accZ[1][0] = pb2v.x; accZ[1][1] = pb2v.y;
        accU[0][0] = accU[0][1] = accU[1][0] = accU[1][1] = 0ull;

        const ulonglong2* __restrict__ pW2 =
            (const ulonglong2*)(W2 + n0 + d0);
        const ulonglong2* __restrict__ pE =
            (const ulonglong2*)(g_E + n0 + d0);
        const float* __restrict__ ph = s_h1t + r0;

        #pragma unroll 4
        for (int k = 0; k < Hm; k++) {
            const ull a2 = *(const ull*)(ph + k * H1P);   // rows r0, r0+1
            float a0, a1; unpack2(a2, a0, a1);
            const float g0 = fmaf(-a0, a0, 1.f);
            const float g1 = fmaf(-a1, a1, 1.f);
            const ull pa0 = pack2(a0, a0), pa1 = pack2(a1, a1);
            const ull pg0 = pack2(g0, g0), pg1 = pack2(g1, g1);
            const ulonglong2 w = pW2[(size_t)k * (Hm / 4)];
            const ulonglong2 e = pE [(size_t)k * (Hm / 4)];
            ffma2(accZ[0][0], pa0, w.x); ffma2(accZ[0][1], pa0, w.y);
            ffma2(accZ[1][0], pa1, w.x); ffma2(accZ[1][1], pa1, w.y);
            ffma2(accU[0][0], pg0, e.x); ffma2(accU[0][1], pg0, e.y);
            ffma2(accU[1][0], pg1, e.x); ffma2(accU[1][1], pg1, e.y);
        }

        // h2 / g2 / div partials; stage h2 transposed [j][r]
        #pragma unroll
        for (int i = 0; i < 2; i++) {
            float dvi = 0.f;
            #pragma unroll
            for (int jp = 0; jp < 2; jp++) {
                float zl, zh, ul, uh;
                unpack2(accZ[i][jp], zl, zh);
                unpack2(accU[i][jp], ul, uh);
                const float hl = tanhf(zl), hh = tanhf(zh);
                const float gl = fmaf(-hl, hl, 1.f);
                const float gh = fmaf(-hh, hh, 1.f);
                dvi = fmaf(gl, ul, dvi);
                dvi = fmaf(gh, uh, dvi);
                s_st[(d0 + 2 * jp)     * STP + r0 + i] = hl;
                s_st[(d0 + 2 * jp + 1) * STP + r0 + i] = hh;
            }
            if (i == 0) dv0 += dvi; else dv1 += dvi;
        }
        __syncthreads();

        // accDX += h2_chunk @ W3[n0:n0+64, :]
        const ulonglong2* __restrict__ pW3 =
            (const ulonglong2*)(W3 + (size_t)n0 * Dm + d0);
        #pragma unroll 4
        for (int kk = 0; kk < 64; kk++) {
            const ull a2 = *(const ull*)(s_st + kk * STP + r0);
            float a0, a1; unpack2(a2, a0, a1);
            const ull pa0 = pack2(a0, a0), pa1 = pack2(a1, a1);
            const ulonglong2 w = pW3[(size_t)kk * (Dm / 4)];
            ffma2(accDX[0][0], pa0, w.x); ffma2(accDX[0][1], pa0, w.y);
            ffma2(accDX[1][0], pa1, w.x); ffma2(accDX[1][1], pa1, w.y);
        }
        __syncthreads();
    }

    // ---- epilogue ----
    atomicAdd(&s_div[r0],     dv0);
    atomicAdd(&s_div[r0 + 1], dv1);

    const float4 b3v = *(const float4*)(b3 + d0);
    #pragma unroll
    for (int i = 0; i < 2; i++) {
        float x0, x1, x2, x3;
        unpack2(accDX[i][0], x0, x1);
        unpack2(accDX[i][1], x2, x3);
        const size_t ro = (size_t)(row0 + r0 + i) * 65 + d0;
        out[ro + 0] = x0 + b3v.x;
        out[ro + 1] = x1 + b3v.y;
        out[ro + 2] = x2 + b3v.z;
        out[ro + 3] = x3 + b3v.w;
    }
    __syncthreads();
    if (tid < MT)
        out[(size_t)(row0 + tid) * 65 + 64] = s_div[tid];
}

// ---------------------------------------------------------------------------
extern "C" void kernel_launch(void* const* d_in, const int* in_sizes, int n_in,
                              void* d_out, int out_size) {
    const float* t  = (const float*)d_in[0];
    const float* x  = (const float*)d_in[1];
    const float* W1 = (const float*)d_in[2];
    const float* b1 = (const float*)d_in[3];
    const float* W2 = (const float*)d_in[4];
    const float* b2 = (const float*)d_in[5];
    const float* W3 = (const float*)d_in[6];
    const float* b3 = (const float*)d_in[7];
    float* out = (float*)d_out;

    compute_E_kernel<<<dim3(16, 16), 256>>>(W1, W2, W3);

    const int smem_bytes =
        (65 * 32 + 512 * H1P + 64 * STP + 32) * (int)sizeof(float);
    cudaFuncSetAttribute(cnf_main_kernel,
                         cudaFuncAttributeMaxDynamicSharedMemorySize, smem_bytes);
    cnf_main_kernel<<<8192 / MT, 256, smem_bytes>>>(t, x, W1, b1, W2, b2,
                                                    W3, b3, out);
}